// round 2
// baseline (speedup 1.0000x reference)
#include <cuda_runtime.h>

#define B 32
#define L 4096
#define D 768
#define WINDOW 32
#define LN_EPS 1e-5f
#define NTHREADS 768
#define NWARPS (NTHREADS / 32)

__global__ __launch_bounds__(NTHREADS, 1)
void vdp_kernel(const float* __restrict__ ref_repr,
                const float* __restrict__ alt_repr,
                const int* __restrict__ variant_pos,
                const float* __restrict__ gamma,
                const float* __restrict__ beta,
                float* __restrict__ out) {
    const int b = blockIdx.x;
    const int d = threadIdx.x;          // 0..767, one channel per thread
    const int lane = d & 31;
    const int warp = d >> 5;

    const int p = variant_pos[b];
    const int lo = max(0, p - WINDOW);
    const int hi = min(L - 1, p + WINDOW);
    const float inv_count = 1.0f / (float)(hi - lo + 1);

    const float* __restrict__ rb = ref_repr + (size_t)b * L * D + (size_t)lo * D + d;
    const float* __restrict__ ab = alt_repr + (size_t)b * L * D + (size_t)lo * D + d;

    // Accumulate alt - ref over the valid window. Loads across iterations are
    // independent -> high MLP; consecutive threads hit consecutive addresses.
    float s = 0.0f;
    const int n = hi - lo + 1;
    int i = 0;
    #pragma unroll 4
    for (; i + 4 <= n; i += 4) {
        float a0 = ab[(size_t)(i + 0) * D], r0 = rb[(size_t)(i + 0) * D];
        float a1 = ab[(size_t)(i + 1) * D], r1 = rb[(size_t)(i + 1) * D];
        float a2 = ab[(size_t)(i + 2) * D], r2 = rb[(size_t)(i + 2) * D];
        float a3 = ab[(size_t)(i + 3) * D], r3 = rb[(size_t)(i + 3) * D];
        s += (a0 - r0) + (a1 - r1) + (a2 - r2) + (a3 - r3);
    }
    for (; i < n; ++i)
        s += ab[(size_t)i * D] - rb[(size_t)i * D];

    const float pooled = s * inv_count;

    // Block reduction over D for mean and mean-of-squares.
    __shared__ float red_s[NWARPS];
    __shared__ float red_q[NWARPS];
    __shared__ float mu_sh, rstd_sh;

    float vs = pooled;
    float vq = pooled * pooled;
    #pragma unroll
    for (int off = 16; off > 0; off >>= 1) {
        vs += __shfl_down_sync(0xffffffffu, vs, off);
        vq += __shfl_down_sync(0xffffffffu, vq, off);
    }
    if (lane == 0) { red_s[warp] = vs; red_q[warp] = vq; }
    __syncthreads();

    if (warp == 0) {
        float ts = (lane < NWARPS) ? red_s[lane] : 0.0f;
        float tq = (lane < NWARPS) ? red_q[lane] : 0.0f;
        #pragma unroll
        for (int off = 16; off > 0; off >>= 1) {
            ts += __shfl_down_sync(0xffffffffu, ts, off);
            tq += __shfl_down_sync(0xffffffffu, tq, off);
        }
        if (lane == 0) {
            const float mu = ts * (1.0f / (float)D);
            const float var = tq * (1.0f / (float)D) - mu * mu;
            mu_sh = mu;
            rstd_sh = rsqrtf(var + LN_EPS);
        }
    }
    __syncthreads();

    out[(size_t)b * D + d] = (pooled - mu_sh) * rstd_sh * gamma[d] + beta[d];
}

extern "C" void kernel_launch(void* const* d_in, const int* in_sizes, int n_in,
                              void* d_out, int out_size) {
    const float* ref_repr    = (const float*)d_in[0];
    const float* alt_repr    = (const float*)d_in[1];
    const int*   variant_pos = (const int*)d_in[2];
    const float* gamma       = (const float*)d_in[3];
    const float* beta        = (const float*)d_in[4];
    float* out = (float*)d_out;

    vdp_kernel<<<B, NTHREADS>>>(ref_repr, alt_repr, variant_pos, gamma, beta, out);
}

// round 3
// speedup vs baseline: 1.2316x; 1.2316x over previous
#include <cuda_runtime.h>

#define B 32
#define L 4096
#define D 768
#define DG (D / 4)            // 192 float4 channel groups
#define WINDOW 32
#define LN_EPS 1e-5f
#define S 8                   // window splits per batch
#define K2_THREADS DG
#define K2_WARPS (K2_THREADS / 32)

// Partial pooled sums: [B][S][DG] float4 (no dynamic alloc allowed)
__device__ float4 vdp_scratch[B * S * DG];

__global__ __launch_bounds__(DG, 8)
void vdp_pool_partial(const float* __restrict__ ref_repr,
                      const float* __restrict__ alt_repr,
                      const int* __restrict__ variant_pos) {
    const int s = blockIdx.x;       // split index 0..S-1
    const int b = blockIdx.y;       // batch
    const int c = threadIdx.x;      // channel group 0..191 (channels 4c..4c+3)

    const int p  = variant_pos[b];
    const int lo = max(0, p - WINDOW);
    const int hi = min(L - 1, p + WINDOW);
    const int n  = hi - lo + 1;     // 33..65 valid rows

    const float4* __restrict__ rb =
        (const float4*)(ref_repr) + (size_t)b * L * DG + (size_t)lo * DG + c;
    const float4* __restrict__ ab =
        (const float4*)(alt_repr) + (size_t)b * L * DG + (size_t)lo * DG + c;

    float4 acc = make_float4(0.f, 0.f, 0.f, 0.f);
    // Strided row assignment: split s handles rows s, s+S, s+2S, ... (<= 9 rows).
    #pragma unroll 3
    for (int i = s; i < n; i += S) {
        float4 a = ab[(size_t)i * DG];
        float4 r = rb[(size_t)i * DG];
        acc.x += a.x - r.x;
        acc.y += a.y - r.y;
        acc.z += a.z - r.z;
        acc.w += a.w - r.w;
    }
    vdp_scratch[((size_t)b * S + s) * DG + c] = acc;
}

__global__ __launch_bounds__(K2_THREADS, 1)
void vdp_finalize(const int* __restrict__ variant_pos,
                  const float* __restrict__ gamma,
                  const float* __restrict__ beta,
                  float* __restrict__ out) {
    const int b = blockIdx.x;
    const int c = threadIdx.x;      // channel group
    const int lane = c & 31;
    const int warp = c >> 5;

    const int p  = variant_pos[b];
    const int lo = max(0, p - WINDOW);
    const int hi = min(L - 1, p + WINDOW);
    const float inv_count = 1.0f / (float)(hi - lo + 1);

    // Fold S partials (L2-resident scratch).
    const float4* __restrict__ sc = vdp_scratch + (size_t)b * S * DG + c;
    float4 acc = make_float4(0.f, 0.f, 0.f, 0.f);
    #pragma unroll
    for (int s = 0; s < S; ++s) {
        float4 v = sc[(size_t)s * DG];
        acc.x += v.x; acc.y += v.y; acc.z += v.z; acc.w += v.w;
    }
    float4 pooled;
    pooled.x = acc.x * inv_count;
    pooled.y = acc.y * inv_count;
    pooled.z = acc.z * inv_count;
    pooled.w = acc.w * inv_count;

    // LayerNorm reduction over D (sum and sum of squares).
    float vs = pooled.x + pooled.y + pooled.z + pooled.w;
    float vq = pooled.x * pooled.x + pooled.y * pooled.y
             + pooled.z * pooled.z + pooled.w * pooled.w;

    __shared__ float red_s[K2_WARPS];
    __shared__ float red_q[K2_WARPS];
    __shared__ float mu_sh, rstd_sh;

    #pragma unroll
    for (int off = 16; off > 0; off >>= 1) {
        vs += __shfl_down_sync(0xffffffffu, vs, off);
        vq += __shfl_down_sync(0xffffffffu, vq, off);
    }
    if (lane == 0) { red_s[warp] = vs; red_q[warp] = vq; }
    __syncthreads();

    if (warp == 0) {
        float ts = (lane < K2_WARPS) ? red_s[lane] : 0.0f;
        float tq = (lane < K2_WARPS) ? red_q[lane] : 0.0f;
        #pragma unroll
        for (int off = 4; off > 0; off >>= 1) {
            ts += __shfl_down_sync(0xffffffffu, ts, off);
            tq += __shfl_down_sync(0xffffffffu, tq, off);
        }
        if (lane == 0) {
            const float mu  = ts * (1.0f / (float)D);
            const float var = tq * (1.0f / (float)D) - mu * mu;
            mu_sh   = mu;
            rstd_sh = rsqrtf(var + LN_EPS);
        }
    }
    __syncthreads();

    const float mu   = mu_sh;
    const float rstd = rstd_sh;
    const float4 g = ((const float4*)gamma)[c];
    const float4 be = ((const float4*)beta)[c];
    float4 o;
    o.x = (pooled.x - mu) * rstd * g.x + be.x;
    o.y = (pooled.y - mu) * rstd * g.y + be.y;
    o.z = (pooled.z - mu) * rstd * g.z + be.z;
    o.w = (pooled.w - mu) * rstd * g.w + be.w;
    ((float4*)out)[(size_t)b * DG + c] = o;
}

extern "C" void kernel_launch(void* const* d_in, const int* in_sizes, int n_in,
                              void* d_out, int out_size) {
    const float* ref_repr    = (const float*)d_in[0];
    const float* alt_repr    = (const float*)d_in[1];
    const int*   variant_pos = (const int*)d_in[2];
    const float* gamma       = (const float*)d_in[3];
    const float* beta        = (const float*)d_in[4];
    float* out = (float*)d_out;

    dim3 grid1(S, B);
    vdp_pool_partial<<<grid1, DG>>>(ref_repr, alt_repr, variant_pos);
    vdp_finalize<<<B, K2_THREADS>>>(variant_pos, gamma, beta, out);
}